// round 2
// baseline (speedup 1.0000x reference)
#include <cuda_runtime.h>
#include <cstdint>

// TopKRouter: logits = x @ W + b ; softmax over E=64 ; top-2 (idx, vals)
// x: (16384, 2048) fp32, W: (2048, 64) fp32, b: (64,)
// out (float32): [0 .. 2M)      = topk_idx as float, row-major (M,2)
//                [2M .. 4M)     = topk_vals,          row-major (M,2)

#define DK 2048
#define NE 64
#define KC 32
#define MT 64
#define NTHREADS 256

__device__ __forceinline__ unsigned long long pk2(float lo, float hi) {
    unsigned long long r;
    asm("mov.b64 %0, {%1, %2};" : "=l"(r) : "f"(lo), "f"(hi));
    return r;
}
__device__ __forceinline__ unsigned long long fma2(unsigned long long a,
                                                   unsigned long long b,
                                                   unsigned long long c) {
    unsigned long long d;
    asm("fma.rn.f32x2 %0, %1, %2, %3;" : "=l"(d) : "l"(a), "l"(b), "l"(c));
    return d;
}
__device__ __forceinline__ float2 unpk(unsigned long long v) {
    float2 f;
    asm("mov.b64 {%0, %1}, %2;" : "=f"(f.x), "=f"(f.y) : "l"(v));
    return f;
}

__global__ __launch_bounds__(NTHREADS)
void router_kernel(const float* __restrict__ x,
                   const float* __restrict__ W,
                   const float* __restrict__ bias,
                   float* __restrict__ out,
                   int M)
{
    // smem: first KC*NE floats = W chunk [KC][NE]; next MT*KC = x chunk [MT][KC].
    // After the K loop the whole region is reused as logits [MT][NE+1] (padded).
    __shared__ float sm[MT * (NE + 1)];
    float* Ws = sm;             // [KC][NE]  = 2048 floats
    float* Xs = sm + KC * NE;   // [MT][KC]  = 2048 floats

    const int tid = threadIdx.x;
    const int tm4 = (tid >> 4) * 4;   // token base within tile (0..60)
    const int te4 = (tid & 15) * 4;   // expert base (0..60)
    const int m0  = blockIdx.x * MT;  // global token base

    unsigned long long acc[4][2];
#pragma unroll
    for (int i = 0; i < 4; i++) { acc[i][0] = 0ull; acc[i][1] = 0ull; }

    for (int k0 = 0; k0 < DK; k0 += KC) {
        __syncthreads();
        // Load W chunk: 2048 contiguous floats = 512 float4
        {
            const float4* wg = (const float4*)(W + (size_t)k0 * NE);
            ((float4*)Ws)[tid]       = wg[tid];
            ((float4*)Ws)[tid + 256] = wg[tid + 256];
        }
        // Load x chunk: 64 tokens x 32 k = 512 float4
#pragma unroll
        for (int r = 0; r < 2; r++) {
            int j  = tid + r * 256;       // 0..511
            int m  = j >> 3;              // token in tile
            int kq = j & 7;               // float4 within the 32-k chunk
            float4 v = *(const float4*)(x + (size_t)(m0 + m) * DK + k0 + kq * 4);
            *(float4*)&Xs[m * KC + kq * 4] = v;
        }
        __syncthreads();

#pragma unroll
        for (int kc = 0; kc < KC; kc += 4) {
            float4 xv[4];
            ulonglong2 wv[4];
#pragma unroll
            for (int i = 0; i < 4; i++)
                xv[i] = *(const float4*)&Xs[(tm4 + i) * KC + kc];
#pragma unroll
            for (int j = 0; j < 4; j++)
                wv[j] = *(const ulonglong2*)&Ws[(kc + j) * NE + te4];
#pragma unroll
            for (int j = 0; j < 4; j++) {
#pragma unroll
                for (int i = 0; i < 4; i++) {
                    const float* xf = (const float*)&xv[i];
                    unsigned long long xx = pk2(xf[j], xf[j]);
                    acc[i][0] = fma2(xx, wv[j].x, acc[i][0]);
                    acc[i][1] = fma2(xx, wv[j].y, acc[i][1]);
                }
            }
        }
    }

    __syncthreads();
    // Write logits (+bias) into padded smem [MT][NE+1]
    {
        float4 bv = *(const float4*)(bias + te4);
        const float* bf = (const float*)&bv;
#pragma unroll
        for (int i = 0; i < 4; i++) {
            float2 a0 = unpk(acc[i][0]);
            float2 a1 = unpk(acc[i][1]);
            float* row = sm + (tm4 + i) * (NE + 1);
            row[te4 + 0] = a0.x + bf[0];
            row[te4 + 1] = a0.y + bf[1];
            row[te4 + 2] = a1.x + bf[2];
            row[te4 + 3] = a1.y + bf[3];
        }
    }
    __syncthreads();

    // One thread per token: softmax + top-2
    if (tid < MT) {
        const float* row = sm + tid * (NE + 1);
        float v1 = -3.402823466e38f; int i1 = 0;
        float v2 = -3.402823466e38f; int i2 = 0;
#pragma unroll 8
        for (int e = 0; e < NE; e++) {
            float v = row[e];
            if (v > v1)      { v2 = v1; i2 = i1; v1 = v; i1 = e; }
            else if (v > v2) { v2 = v;  i2 = e; }
        }
        float s = 0.f;
#pragma unroll 8
        for (int e = 0; e < NE; e++) s += __expf(row[e] - v1);
        float p1 = 1.0f / s;              // exp(v1-v1)/s
        float p2 = __expf(v2 - v1) / s;

        int g = m0 + tid;
        out[2 * g + 0] = (float)i1;
        out[2 * g + 1] = (float)i2;
        size_t voff = (size_t)2 * M;
        out[voff + 2 * g + 0] = p1;
        out[voff + 2 * g + 1] = p2;
    }
}

extern "C" void kernel_launch(void* const* d_in, const int* in_sizes, int n_in,
                              void* d_out, int out_size) {
    const float* x  = (const float*)d_in[0];
    const float* W  = (const float*)d_in[1];
    const float* b  = (const float*)d_in[2];
    float* out = (float*)d_out;

    int M = in_sizes[0] / DK;   // 16384 tokens
    dim3 grid(M / MT);
    router_kernel<<<grid, NTHREADS>>>(x, W, b, out, M);
}